// round 16
// baseline (speedup 1.0000x reference)
#include <cuda_runtime.h>
#include <math.h>

// Problem constants
#define RADIUS   512
#define DIAM     1024
#define N_WL     31
#define NPIX     (DIAM * DIAM)            // 1048576
#define NTOT     (NPIX * N_WL)            // 32505856
#define NVEC     (NTOT / 4)               // 8126464 float4 groups
#define NPIX8    (NPIX / 8)               // 131072

#define BLOCK      256
#define GRP_PER_THD 4
#define GRP_PER_BLK (BLOCK * GRP_PER_THD) // 1024 float4 groups per block

// Single-test conservative threshold on d2(p0) = dx^2+dy^2 covering BOTH p0
// and p1=p0+1 (proven in R14/15): same-row shift <= 1025; row-wrap inside
// case has d2(p0)=261122 < threshold. 262144 + 1025 + margin -> 263500.
// guess is a strict superset of the true per-group aperture.
#define D2_GUESS 263500

// Device globals (no allocation allowed)
__device__ float g_kdn[N_WL];   // k * delta_n per wavelength
__device__ float g_hm[NPIX];    // hmap+noise if inside (>0), -1 if outside

// ---------------------------------------------------------------------------
// Prologue kernel (8 pixels/thread, vectorized). Reads the REAL rad input
// (R9: radius_distance is NOT reconstructible bit-exactly on device).
// ---------------------------------------------------------------------------
__global__ void __launch_bounds__(256)
doe_pre_kernel(const float*  __restrict__ hmw,
               const float*  __restrict__ wl,
               const float4* __restrict__ noise4,
               const float4* __restrict__ rad4)
{
    int t = blockIdx.x * blockDim.x + threadIdx.x;

    if (t < N_WL) {
        float l  = __ldg(&wl[t]);
        float dn = __fsub_rn(__fadd_rn(1.5f, __fdiv_rn(4e-15f, __fmul_rn(l, l))), 1.0f);
        float k  = __fdiv_rn(6.283185307179586f, l);
        g_kdn[t] = __fmul_rn(k, dn);
    }

    if (t >= NPIX8) return;

    const float lam0 = 7e-07f;
    float n0 = __fadd_rn(1.5f, __fdiv_rn(4e-15f, __fmul_rn(lam0, lam0)));
    float q  = __fdiv_rn(lam0, __fsub_rn(n0, 1.0f));

    int v0 = t * 2;
    float4 ra = __ldcs(&rad4[v0]);
    float4 rb = __ldcs(&rad4[v0 + 1]);
    float4 na = __ldcs(&noise4[v0]);
    float4 nb = __ldcs(&noise4[v0 + 1]);

    float rr[8] = {ra.x, ra.y, ra.z, ra.w, rb.x, rb.y, rb.z, rb.w};
    float nn[8] = {na.x, na.y, na.z, na.w, nb.x, nb.y, nb.z, nb.w};

    float o[8];
#pragma unroll
    for (int j = 0; j < 8; j++) {
        float r = rr[j];
        int idx = (int)ceilf(r) - 1;
        idx = min(max(idx, 0), RADIUS - 1);
        float x = fminf(fmaxf(__ldg(&hmw[idx]), -1.0f), 1.0f);
        float normed = __fmul_rn(__fadd_rn(x, 1.0f), 0.5f);
        float tb = __fsub_rn(0.002f, __fmul_rn(q, normed));
        float hm = __fadd_rn(tb, nn[j]);          // inside value (> 0)
        o[j] = (r <= 512.0f) ? hm : -1.0f;        // sign encodes aperture
    }

    float4* dst = (float4*)&g_hm[t * 8];
    dst[0] = make_float4(o[0], o[1], o[2], o[3]);
    dst[1] = make_float4(o[4], o[5], o[6], o[7]);
}

// ---------------------------------------------------------------------------
// Main kernel (PDL secondary). Pre-wait phase: index math, guess-gated
// stream loads, zero-stores for dead groups — all independent of g_hm, and
// overlapped with doe_pre_kernel via programmatic stream serialization.
// griddepcontrol.wait then releases the exact g_hm reads (no-op if PDL is
// not engaged; stream order still guarantees correctness).
// ---------------------------------------------------------------------------
__global__ void __launch_bounds__(BLOCK)
doe_main_kernel(const float4* __restrict__ fr,
                const float4* __restrict__ fi,
                float4* __restrict__ out)
{
    // ---- Phase A: ONE division, then incremental indices + 1 test/group ----
    const int gbase = blockIdx.x * GRP_PER_BLK + threadIdx.x;
    const unsigned int b0   = (unsigned int)gbase * 4u;
    const unsigned int q0   = b0 / 31u;            // magic-multiply (once)
    const unsigned int rem0 = b0 - q0 * 31u;

    int          g[GRP_PER_THD];
    unsigned int w0[GRP_PER_THD];
    unsigned int p0a[GRP_PER_THD];
    bool         guess[GRP_PER_THD];

#pragma unroll
    for (int k = 0; k < GRP_PER_THD; k++) {
        g[k] = gbase + k * BLOCK;
        unsigned int rw    = rem0 + (unsigned int)k;     // <= 34
        unsigned int carry = (rw >= 31u) ? 1u : 0u;
        unsigned int p0    = q0 + 33u * (unsigned int)k + carry;
        w0[k]  = rw - 31u * carry;
        p0a[k] = p0;

        int dx = (int)(p0 & 1023u) - 512;
        int dy = (int)(p0 >> 10)   - 512;
        guess[k] = (dx * dx + dy * dy) <= D2_GUESS;
    }

    // ---- Phase B: guess-gated stream loads + zero-stores (no g_hm dep) ----
    float4 vr[GRP_PER_THD], vi[GRP_PER_THD];
#pragma unroll
    for (int k = 0; k < GRP_PER_THD; k++) {
        vr[k] = vi[k] = make_float4(0.f, 0.f, 0.f, 0.f);
        if (guess[k]) { vr[k] = __ldcs(&fr[g[k]]); vi[k] = __ldcs(&fi[g[k]]); }
    }
#pragma unroll
    for (int k = 0; k < GRP_PER_THD; k++) {
        if (!guess[k]) {
            // guess superset of live: both pixels outside -> exact zeros.
            float4 z = make_float4(0.f, 0.f, 0.f, 0.f);
            __stcs(&out[g[k]], z);  __stcs(&out[NVEC + g[k]], z);
        }
    }

    // ---- Wait for doe_pre_kernel's g_hm / g_kdn ----
    asm volatile("griddepcontrol.wait;" ::: "memory");

    const float INV2PI = 0.15915494309189535f;
    const float PI2_HI = 6.28318548202514648f;     // fl32(2*pi)
    const float PI2_LO = -1.74845553146957e-7f;    // 2*pi - fl32(2*pi)

#pragma unroll
    for (int k = 0; k < GRP_PER_THD; k++) {
        if (!guess[k]) continue;

        unsigned int p0 = p0a[k];
        unsigned int p1 = (p0 + 1u < NPIX) ? p0 + 1u : p0;
        float vA = g_hm[p0];                        // broadcast L1/L2 hits
        float vB = g_hm[p1];
        bool inA = (vA > 0.0f);
        bool inB = (vB > 0.0f);

        if (!(inA | inB)) {
            float4 z = make_float4(0.f, 0.f, 0.f, 0.f);
            __stcs(&out[g[k]], z);  __stcs(&out[NVEC + g[k]], z);
            continue;
        }

        float oR[4], oI[4];
        float xr4[4] = {vr[k].x, vr[k].y, vr[k].z, vr[k].w};
        float xi4[4] = {vi[k].x, vi[k].y, vi[k].z, vi[k].w};

#pragma unroll
        for (int j = 0; j < 4; j++) {
            unsigned int w = w0[k] + j;
            bool wrap = (w >= N_WL);
            unsigned int wr = wrap ? w - N_WL : w;
            float hm = wrap ? vB : vA;
            float a  = (wrap ? inB : inA) ? 1.0f : 0.0f;

            float phase = __fmul_rn(g_kdn[wr], hm);    // bit-matches reference

            float nf = rintf(__fmul_rn(phase, INV2PI));
            float rr = fmaf(-nf, PI2_HI, phase);
            rr = fmaf(-nf, PI2_LO, rr);

            float s, c;
            __sincosf(rr, &s, &c);

            float xr = xr4[j], xi = xi4[j];
            oR[j] = (xr * c - xi * s) * a;
            oI[j] = (xr * s + xi * c) * a;
        }

        __stcs(&out[g[k]],        make_float4(oR[0], oR[1], oR[2], oR[3]));
        __stcs(&out[NVEC + g[k]], make_float4(oI[0], oI[1], oI[2], oI[3]));
    }
}

// ---------------------------------------------------------------------------
// kernel_launch: inputs in metadata order:
//   0 height_map_weight [512]
//   1 field_real  [1,1024,1024,31]
//   2 field_imag  [1,1024,1024,31]
//   3 wavelength  [31]
//   4 noise       [1,1024,1024,1]
//   5 radius_distance [1024,1024]
//   6 aperture    [1024,1024]   (derived on device: ap == (rad <= 512))
// output: [2,1,1024,1024,31] float32
// ---------------------------------------------------------------------------
extern "C" void kernel_launch(void* const* d_in, const int* in_sizes, int n_in,
                              void* d_out, int out_size)
{
    const float* hmw   = (const float*)d_in[0];
    const float* fr    = (const float*)d_in[1];
    const float* fi    = (const float*)d_in[2];
    const float* wl    = (const float*)d_in[3];
    const float* noise = (const float*)d_in[4];
    const float* rad   = (const float*)d_in[5];
    float* out = (float*)d_out;

    doe_pre_kernel<<<NPIX8 / 256, 256>>>(hmw, wl,
                                         (const float4*)noise,
                                         (const float4*)rad);

    // PDL secondary: overlap its pre-wait phase with doe_pre_kernel.
    cudaLaunchConfig_t cfg = {};
    cfg.gridDim  = dim3(NVEC / GRP_PER_BLK, 1, 1);   // 7936
    cfg.blockDim = dim3(BLOCK, 1, 1);
    cfg.dynamicSmemBytes = 0;
    cfg.stream = 0;   // same (legacy) stream as the <<<>>> launch above
    cudaLaunchAttribute attrs[1];
    attrs[0].id = cudaLaunchAttributeProgrammaticStreamSerialization;
    attrs[0].val.programmaticStreamSerializationAllowed = 1;
    cfg.attrs = attrs;
    cfg.numAttrs = 1;
    cudaLaunchKernelEx(&cfg, doe_main_kernel,
                       (const float4*)fr, (const float4*)fi, (float4*)out);
}

// round 17
// speedup vs baseline: 1.0527x; 1.0527x over previous
#include <cuda_runtime.h>
#include <math.h>

// Problem constants
#define RADIUS   512
#define DIAM     1024
#define N_WL     31
#define NPIX     (DIAM * DIAM)            // 1048576
#define NTOT     (NPIX * N_WL)            // 32505856
#define NVEC     (NTOT / 4)               // 8126464 float4 groups

#define BLOCK      256
#define GRP_PER_THD 4
#define GRP_PER_BLK (BLOCK * GRP_PER_THD) // 1024 float4 groups per block
// Block spans 4096 elements -> <=134 distinct pixels (incl. p1 of last group)
#define MAX_PIX_BLK 136
// Single-test conservative threshold on d2(p0) = dx^2+dy^2 covering BOTH p0
// and p1=p0+1: same-row adjacency shifts d2 by <= 2*512+1 = 1025; the
// row-wrap case (p0=(r,1023) -> p1=(r+1,0)) only has p1 inside when
// p1=(512,0) (d2=262144), where d2(p0)=511^2+1=261122 < threshold. True
// boundary 262144 + 1025 + margin(rounding) -> 263500. live_guess is a
// strict superset of the true per-group aperture.
#define D2_GUESS 263500

// ---------------------------------------------------------------------------
// Single fused kernel (converged structure, best measured: 73.0us total).
//   Phase A (cheap ALU): ONE magic-div for the thread's first group, then
//     incremental p0/w0 (1024 = 33*31+1 -> +33 and a carry), plus ONE integer
//     circle test per group (widened threshold covers p1).
//   Phase B: issue ALL stream loads gated by the guess - no smem dependency,
//     so they are in flight before the prologue's DRAM latency.
//   Phase C: block prologue - threads 0..30 build kdn, threads 0..135 build
//     the exact per-pixel (hmap+noise | -1) record in smem from the REAL
//     rad/noise inputs (bit-exact fp32 chain; R9: rad is ground truth).
//   Phase D: __syncthreads, then compute with EXACT smem values (aperture
//     zeroing uses the smem sign, not the guess).
// ---------------------------------------------------------------------------
__global__ void __launch_bounds__(BLOCK)
doe_fused_kernel(const float4* __restrict__ fr,
                 const float4* __restrict__ fi,
                 const float*  __restrict__ hmw,
                 const float*  __restrict__ wl,
                 const float*  __restrict__ noise,
                 const float*  __restrict__ rad,
                 float4* __restrict__ out)
{
    __shared__ float s_kdn[N_WL];
    __shared__ float s_pix[MAX_PIX_BLK];   // hm+noise (>0) if inside, -1 outside

    const unsigned int blockBase = (unsigned int)blockIdx.x * (GRP_PER_BLK * 4u);
    const unsigned int pFirst    = blockBase / 31u;

    // ---- Phase A: ONE division, then incremental indices + 1 test/group ----
    const int gbase = blockIdx.x * GRP_PER_BLK + threadIdx.x;
    const unsigned int b0   = (unsigned int)gbase * 4u;
    const unsigned int q0   = b0 / 31u;            // magic-multiply (once)
    const unsigned int rem0 = b0 - q0 * 31u;

    int          g[GRP_PER_THD];
    unsigned int w0[GRP_PER_THD];
    unsigned int pl[GRP_PER_THD];                  // local pixel idx in s_pix
    bool         guess[GRP_PER_THD];

#pragma unroll
    for (int k = 0; k < GRP_PER_THD; k++) {
        g[k] = gbase + k * BLOCK;
        unsigned int rw    = rem0 + (unsigned int)k;     // <= 34
        unsigned int carry = (rw >= 31u) ? 1u : 0u;
        unsigned int p0    = q0 + 33u * (unsigned int)k + carry;
        w0[k] = rw - 31u * carry;
        pl[k] = p0 - pFirst;

        int dx = (int)(p0 & 1023u) - 512;
        int dy = (int)(p0 >> 10)   - 512;
        guess[k] = (dx * dx + dy * dy) <= D2_GUESS;
    }

    // ---- Phase B: issue all stream loads up front (no smem dependency) ----
    float4 vr[GRP_PER_THD], vi[GRP_PER_THD];
#pragma unroll
    for (int k = 0; k < GRP_PER_THD; k++) {
        vr[k] = vi[k] = make_float4(0.f, 0.f, 0.f, 0.f);
        if (guess[k]) { vr[k] = __ldcs(&fr[g[k]]); vi[k] = __ldcs(&fi[g[k]]); }
    }

    // ---- Phase C: block prologue (overlaps with in-flight stream loads) ----
    if (threadIdx.x < N_WL) {
        float l  = __ldg(&wl[threadIdx.x]);
        float dn = __fsub_rn(__fadd_rn(1.5f, __fdiv_rn(4e-15f, __fmul_rn(l, l))), 1.0f);
        float k2 = __fdiv_rn(6.283185307179586f, l);
        s_kdn[threadIdx.x] = __fmul_rn(k2, dn);
    }
    if (threadIdx.x < MAX_PIX_BLK) {
        unsigned int pp = pFirst + threadIdx.x;
        if (pp >= NPIX) pp = NPIX - 1;

        const float lam0 = 7e-07f;
        float n0 = __fadd_rn(1.5f, __fdiv_rn(4e-15f, __fmul_rn(lam0, lam0)));
        float q  = __fdiv_rn(lam0, __fsub_rn(n0, 1.0f));

        float r = __ldg(&rad[pp]);                 // REAL rad (ground truth)
        int idx = (int)ceilf(r) - 1;
        idx = min(max(idx, 0), RADIUS - 1);
        float x = fminf(fmaxf(__ldg(&hmw[idx]), -1.0f), 1.0f);
        float normed = __fmul_rn(__fadd_rn(x, 1.0f), 0.5f);
        float tb = __fsub_rn(0.002f, __fmul_rn(q, normed));
        float hm = __fadd_rn(tb, __ldg(&noise[pp]));   // inside value (> 0)
        s_pix[threadIdx.x] = (r <= 512.0f) ? hm : -1.0f;
    }
    __syncthreads();

    // ---- Phase D: compute with exact smem values ----
    const float INV2PI = 0.15915494309189535f;
    const float PI2_HI = 6.28318548202514648f;     // fl32(2*pi)
    const float PI2_LO = -1.74845553146957e-7f;    // 2*pi - fl32(2*pi)

#pragma unroll
    for (int k = 0; k < GRP_PER_THD; k++) {
        float vA = s_pix[pl[k]];
        float vB = s_pix[pl[k] + 1];
        bool inA = (vA > 0.0f);
        bool inB = (vB > 0.0f);

        if (!(inA | inB)) {
            float4 z = make_float4(0.f, 0.f, 0.f, 0.f);
            __stcs(&out[g[k]], z);  __stcs(&out[NVEC + g[k]], z);
            continue;
        }

        float oR[4], oI[4];
        float xr4[4] = {vr[k].x, vr[k].y, vr[k].z, vr[k].w};
        float xi4[4] = {vi[k].x, vi[k].y, vi[k].z, vi[k].w};

#pragma unroll
        for (int j = 0; j < 4; j++) {
            unsigned int w = w0[k] + j;
            bool wrap = (w >= N_WL);
            unsigned int wr = wrap ? w - N_WL : w;
            float hm = wrap ? vB : vA;
            float a  = (wrap ? inB : inA) ? 1.0f : 0.0f;

            float phase = __fmul_rn(s_kdn[wr], hm);    // bit-matches reference

            float nf = rintf(__fmul_rn(phase, INV2PI));
            float rr = fmaf(-nf, PI2_HI, phase);
            rr = fmaf(-nf, PI2_LO, rr);

            float s, c;
            __sincosf(rr, &s, &c);

            float xr = xr4[j], xi = xi4[j];
            oR[j] = (xr * c - xi * s) * a;
            oI[j] = (xr * s + xi * c) * a;
        }

        __stcs(&out[g[k]],        make_float4(oR[0], oR[1], oR[2], oR[3]));
        __stcs(&out[NVEC + g[k]], make_float4(oI[0], oI[1], oI[2], oI[3]));
    }
}

// ---------------------------------------------------------------------------
// kernel_launch: inputs in metadata order:
//   0 height_map_weight [512]
//   1 field_real  [1,1024,1024,31]
//   2 field_imag  [1,1024,1024,31]
//   3 wavelength  [31]
//   4 noise       [1,1024,1024,1]
//   5 radius_distance [1024,1024]
//   6 aperture    [1024,1024]   (derived on device: ap == (rad <= 512))
// output: [2,1,1024,1024,31] float32
// ---------------------------------------------------------------------------
extern "C" void kernel_launch(void* const* d_in, const int* in_sizes, int n_in,
                              void* d_out, int out_size)
{
    const float* hmw   = (const float*)d_in[0];
    const float* fr    = (const float*)d_in[1];
    const float* fi    = (const float*)d_in[2];
    const float* wl    = (const float*)d_in[3];
    const float* noise = (const float*)d_in[4];
    const float* rad   = (const float*)d_in[5];
    float* out = (float*)d_out;

    const int blocks = NVEC / GRP_PER_BLK;   // 7936 (exact)
    doe_fused_kernel<<<blocks, BLOCK>>>((const float4*)fr,
                                        (const float4*)fi,
                                        hmw, wl, noise, rad,
                                        (float4*)out);
}